// round 16
// baseline (speedup 1.0000x reference)
#include <cuda_runtime.h>
#include <math.h>
#include <stdint.h>

#define BB 2
#define TT 2048
#define CC 2048
#define NH 16
#define NKV 4
#define HD 128
#define GG 4
#define WINDOW 1024
#define SOFTCAP 50.0f
#define TQ 64
#define TK 32

#define MROWS (BB*TT)   // 4096

__device__ float g_Q[MROWS * (NH*HD)];
__device__ float g_K[MROWS * (NKV*HD)];
__device__ float g_V[MROWS * (NKV*HD)];
__device__ float g_E[MROWS * (NH*HD)];

__device__ __forceinline__ uint32_t f2tf32(float x) {
    uint32_t r;
    asm("cvt.rna.tf32.f32 %0, %1;" : "=r"(r) : "f"(x));
    return r;
}

// exp(50*tanh(x/50)): tanh via odd polynomial on the FMA pipe, single MUFU (ex2).
__device__ __forceinline__ float softcap_exp(float x) {
    const float z2 = x * x * (1.0f / 2500.0f);
    float p = -0.053968254f;                 // -17/315
    p = fmaf(p, z2,  0.133333333f);          //  2/15
    p = fmaf(p, z2, -0.333333333f);          // -1/3
    p = fmaf(p, z2,  1.0f);
    float y = x * p;                         // = 50*tanh(x/50)
    y = fminf(fmaxf(y, -SOFTCAP), SOFTCAP);
    float r;
    asm("ex2.approx.f32 %0, %1;" : "=f"(r) : "f"(y * 1.4426950408889634f));
    return r;
}

// ---------------------------------------------------------------------------
// TF32 tensor-core GEMM, double-buffered SMEM.
// 128x128 block tile, BK=16, 128 threads = 4 warps (2m x 2n),
// warp tile 64x64: per 8-k chunk 32 LDS feed 32 MMAs (was 24:16).
// ---------------------------------------------------------------------------
__global__ __launch_bounds__(128, 2) void gemm_tf32(
    const float* __restrict__ A, const float* __restrict__ B,
    float* __restrict__ C, int M, int N, int Kd)
{
    __shared__ float As[2][16][132];   // [k][m], tf32 bits
    __shared__ float Bs[2][16][132];   // [k][n], tf32 bits

    const int tid  = threadIdx.x;      // 0..127
    const int lane = tid & 31;
    const int wid  = tid >> 5;         // 0..3
    const int wm   = wid >> 1;         // 0..1
    const int wn   = wid & 1;          // 0..1
    const int grp  = lane >> 2;        // 0..7
    const int tig  = lane & 3;         // 0..3

    const int row0 = blockIdx.y * 128;
    const int col0 = blockIdx.x * 128;

    // A loader: thread = one row (128 rows), 4 k-float4 each
    const int ar = tid;                // 0..127
    // B loader: thread = (kr, n4); 4 k-rows stride 4
    const int kr = tid >> 5;           // 0..3
    const int n4 = tid & 31;           // 0..31

    const float* Ap = A + (size_t)(row0 + ar) * Kd;
    const float* Bp = B + (size_t)kr * N + col0 + n4 * 4;

    float acc[4][8][4];
    #pragma unroll
    for (int i = 0; i < 4; i++)
        #pragma unroll
        for (int j = 0; j < 8; j++)
            #pragma unroll
            for (int c = 0; c < 4; c++) acc[i][j][c] = 0.0f;

    float4 ga[4], gb[4];
    #pragma unroll
    for (int u = 0; u < 4; u++) {
        ga[u] = *(const float4*)(Ap + u * 4);
        gb[u] = *(const float4*)(Bp + (size_t)(u * 4) * N);
    }

    // stage buffer 0
    #pragma unroll
    for (int u = 0; u < 4; u++) {
        As[0][u*4 + 0][ar] = __uint_as_float(f2tf32(ga[u].x));
        As[0][u*4 + 1][ar] = __uint_as_float(f2tf32(ga[u].y));
        As[0][u*4 + 2][ar] = __uint_as_float(f2tf32(ga[u].z));
        As[0][u*4 + 3][ar] = __uint_as_float(f2tf32(ga[u].w));
        float4 tb;
        tb.x = __uint_as_float(f2tf32(gb[u].x));
        tb.y = __uint_as_float(f2tf32(gb[u].y));
        tb.z = __uint_as_float(f2tf32(gb[u].z));
        tb.w = __uint_as_float(f2tf32(gb[u].w));
        *(float4*)&Bs[0][kr + u*4][n4*4] = tb;
    }
    __syncthreads();

    const int nIter = Kd >> 4;
    for (int it = 0; it < nIter; it++) {
        const int cur = it & 1;
        const bool more = (it + 1 < nIter);

        if (more) {
            #pragma unroll
            for (int u = 0; u < 4; u++) {
                ga[u] = *(const float4*)(Ap + (it + 1) * 16 + u * 4);
                gb[u] = *(const float4*)(Bp + (size_t)((it + 1) * 16 + u * 4) * N);
            }
        }

        #pragma unroll
        for (int kk = 0; kk < 16; kk += 8) {
            uint32_t af[4][4], bf[8][2];
            #pragma unroll
            for (int i = 0; i < 4; i++) {
                const int m0 = wm*64 + i*16 + grp;
                af[i][0] = __float_as_uint(As[cur][kk + tig]    [m0]);
                af[i][1] = __float_as_uint(As[cur][kk + tig]    [m0 + 8]);
                af[i][2] = __float_as_uint(As[cur][kk + tig + 4][m0]);
                af[i][3] = __float_as_uint(As[cur][kk + tig + 4][m0 + 8]);
            }
            #pragma unroll
            for (int j = 0; j < 8; j++) {
                const int n0 = wn*64 + j*8 + grp;
                bf[j][0] = __float_as_uint(Bs[cur][kk + tig]    [n0]);
                bf[j][1] = __float_as_uint(Bs[cur][kk + tig + 4][n0]);
            }
            #pragma unroll
            for (int i = 0; i < 4; i++)
                #pragma unroll
                for (int j = 0; j < 8; j++) {
                    asm volatile(
                        "mma.sync.aligned.m16n8k8.row.col.f32.tf32.tf32.f32 "
                        "{%0,%1,%2,%3}, {%4,%5,%6,%7}, {%8,%9}, {%0,%1,%2,%3};"
                        : "+f"(acc[i][j][0]), "+f"(acc[i][j][1]),
                          "+f"(acc[i][j][2]), "+f"(acc[i][j][3])
                        : "r"(af[i][0]), "r"(af[i][1]), "r"(af[i][2]), "r"(af[i][3]),
                          "r"(bf[j][0]), "r"(bf[j][1]));
                }
        }

        if (more) {
            const int nxt = cur ^ 1;
            #pragma unroll
            for (int u = 0; u < 4; u++) {
                As[nxt][u*4 + 0][ar] = __uint_as_float(f2tf32(ga[u].x));
                As[nxt][u*4 + 1][ar] = __uint_as_float(f2tf32(ga[u].y));
                As[nxt][u*4 + 2][ar] = __uint_as_float(f2tf32(ga[u].z));
                As[nxt][u*4 + 3][ar] = __uint_as_float(f2tf32(ga[u].w));
                float4 tb;
                tb.x = __uint_as_float(f2tf32(gb[u].x));
                tb.y = __uint_as_float(f2tf32(gb[u].y));
                tb.z = __uint_as_float(f2tf32(gb[u].z));
                tb.w = __uint_as_float(f2tf32(gb[u].w));
                *(float4*)&Bs[nxt][kr + u*4][n4*4] = tb;
            }
        }
        __syncthreads();
    }

    #pragma unroll
    for (int i = 0; i < 4; i++) {
        const int row = row0 + wm*64 + i*16 + grp;
        #pragma unroll
        for (int j = 0; j < 8; j++) {
            const int col = col0 + wn*64 + j*8 + tig*2;
            *(float2*)(C + (size_t)row * N + col)       = make_float2(acc[i][j][0], acc[i][j][1]);
            *(float2*)(C + (size_t)(row + 8) * N + col) = make_float2(acc[i][j][2], acc[i][j][3]);
        }
    }
}

// ---------------------------------------------------------------------------
// RoPE: 256 threads, 4 (row,head) units per block.
// ---------------------------------------------------------------------------
__global__ __launch_bounds__(256) void rope_kernel(float* data, int nheads)
{
    const int tid  = threadIdx.x;
    const int unit = blockIdx.x * 4 + (tid >> 6);
    const int i    = tid & 63;

    const int h   = unit % nheads;
    const int row = unit / nheads;
    const int t   = row % TT;

    float* p = data + (size_t)row * nheads * HD + h * HD;

    const float a = (float)t * exp2f(-(float)i * (13.287712379549449f / 64.0f));
    float c, s;
    __sincosf(a, &s, &c);

    const float x1 = p[i];
    const float x2 = p[i + 64];
    p[i]      = x1 * c - x2 * s;
    p[i + 64] = x2 * c + x1 * s;
}

// ---------------------------------------------------------------------------
// Flash-tiled attention (unchanged from round 15, passing at occ 2).
// ---------------------------------------------------------------------------
struct AttnSmem {
    float Q[TQ][132];        // tf32, pre-scaled
    float K[TK][132];        // tf32
    float V[TK][132];        // tf32
    float P[TQ][36];         // tf32 probs for current key tile
    float rowsum[2][TQ];
};

__global__ __launch_bounds__(256, 2) void attn_kernel(
    const float* __restrict__ Q, const float* __restrict__ K,
    const float* __restrict__ V, float* __restrict__ E)
{
    extern __shared__ float smem_raw[];
    AttnSmem& sm = *reinterpret_cast<AttnSmem*>(smem_raw);

    const int tid  = threadIdx.x;
    const int qt   = blockIdx.x;
    const int head = blockIdx.y;
    const int b    = blockIdx.z;
    const int kv   = head >> 2;
    const int q0   = qt * TQ;
    const int rowbase = b * TT;

    const float scale = 0.08838834764831845f;  // 128^-0.5

    // stage Q tile (scaled, tf32)
    for (int i = tid; i < 2048; i += 256) {
        const int r = i >> 5, c4 = i & 31;
        float4 v = *(const float4*)(Q + (size_t)(rowbase + q0 + r) * (NH*HD) + head*HD + c4*4);
        float4 tv;
        tv.x = __uint_as_float(f2tf32(v.x * scale));
        tv.y = __uint_as_float(f2tf32(v.y * scale));
        tv.z = __uint_as_float(f2tf32(v.z * scale));
        tv.w = __uint_as_float(f2tf32(v.w * scale));
        *(float4*)&sm.Q[r][c4*4] = tv;
    }

    const int lane = tid & 31, wid = tid >> 5;
    const int wm = wid >> 1, wn = wid & 1;
    const int grp = lane >> 2, quad = lane & 3;
    const int r0 = wm*16 + grp;
    const int t_lo = q0 + r0;
    const int t_hi = t_lo + 8;

    __syncthreads();

    // ---- hoist Q A-fragments for k-steps 0..7 into registers (once per block)
    uint32_t qa[8][4];
    #pragma unroll
    for (int ks = 0; ks < 8; ks++) {
        qa[ks][0] = __float_as_uint(sm.Q[r0]    [ks*8 + quad]);
        qa[ks][1] = __float_as_uint(sm.Q[r0 + 8][ks*8 + quad]);
        qa[ks][2] = __float_as_uint(sm.Q[r0]    [ks*8 + quad + 4]);
        qa[ks][3] = __float_as_uint(sm.Q[r0 + 8][ks*8 + quad + 4]);
    }

    int s_begin = q0 - WINDOW; if (s_begin < 0) s_begin = 0;
    const int s_end  = q0 + TQ - 1;
    const int ntiles = (s_end - s_begin) / TK + 1;

    float lsum0 = 0.0f, lsum1 = 0.0f;

    float cpv[8][4];
    #pragma unroll
    for (int j = 0; j < 8; j++)
        #pragma unroll
        for (int c = 0; c < 4; c++) cpv[j][c] = 0.0f;

    for (int tile = 0; tile < ntiles; tile++) {
        const int s0 = s_begin + tile * TK;

        __syncthreads();   // prev tile's K/V/P fully consumed

        // stage K and V tiles (both tf32): 2048 float4
        for (int i = tid; i < 2048; i += 256) {
            const int which = i >> 10;
            const int j = i & 1023;
            const int r = j >> 5, c4 = j & 31;
            int srow = s0 + r; if (srow > TT-1) srow = TT-1;
            const float* src = which ? V : K;
            float4 v = *(const float4*)(src + (size_t)(rowbase + srow) * (NKV*HD) + kv*HD + c4*4);
            float4 tv;
            tv.x = __uint_as_float(f2tf32(v.x));
            tv.y = __uint_as_float(f2tf32(v.y));
            tv.z = __uint_as_float(f2tf32(v.z));
            tv.w = __uint_as_float(f2tf32(v.w));
            if (which) *(float4*)&sm.V[r][c4*4] = tv;
            else       *(float4*)&sm.K[r][c4*4] = tv;
        }
        __syncthreads();

        // ---- S = Q K^T (warp tile 16x16)
        float c[2][4];
        #pragma unroll
        for (int n = 0; n < 2; n++)
            #pragma unroll
            for (int i = 0; i < 4; i++) c[n][i] = 0.0f;

        // k-steps 0..7: Q frags from registers
        #pragma unroll
        for (int ks = 0; ks < 8; ks++) {
            #pragma unroll
            for (int n = 0; n < 2; n++) {
                const int key = wn*16 + n*8 + grp;
                const uint32_t b0 = __float_as_uint(sm.K[key][ks*8 + quad]);
                const uint32_t b1 = __float_as_uint(sm.K[key][ks*8 + quad + 4]);
                asm volatile(
                    "mma.sync.aligned.m16n8k8.row.col.f32.tf32.tf32.f32 "
                    "{%0,%1,%2,%3}, {%4,%5,%6,%7}, {%8,%9}, {%0,%1,%2,%3};"
                    : "+f"(c[n][0]), "+f"(c[n][1]), "+f"(c[n][2]), "+f"(c[n][3])
                    : "r"(qa[ks][0]), "r"(qa[ks][1]), "r"(qa[ks][2]), "r"(qa[ks][3]),
                      "r"(b0), "r"(b1));
            }
        }
        // k-steps 8..15: Q frags from SMEM
        #pragma unroll
        for (int ks = 8; ks < 16; ks++) {
            const uint32_t a0 = __float_as_uint(sm.Q[r0]    [ks*8 + quad]);
            const uint32_t a1 = __float_as_uint(sm.Q[r0 + 8][ks*8 + quad]);
            const uint32_t a2 = __float_as_uint(sm.Q[r0]    [ks*8 + quad + 4]);
            const uint32_t a3 = __float_as_uint(sm.Q[r0 + 8][ks*8 + quad + 4]);
            #pragma unroll
            for (int n = 0; n < 2; n++) {
                const int key = wn*16 + n*8 + grp;
                const uint32_t b0 = __float_as_uint(sm.K[key][ks*8 + quad]);
                const uint32_t b1 = __float_as_uint(sm.K[key][ks*8 + quad + 4]);
                asm volatile(
                    "mma.sync.aligned.m16n8k8.row.col.f32.tf32.tf32.f32 "
                    "{%0,%1,%2,%3}, {%4,%5,%6,%7}, {%8,%9}, {%0,%1,%2,%3};"
                    : "+f"(c[n][0]), "+f"(c[n][1]), "+f"(c[n][2]), "+f"(c[n][3])
                    : "r"(a0), "r"(a1), "r"(a2), "r"(a3), "r"(b0), "r"(b1));
            }
        }

        // ---- softcap + mask + exp -> P (tf32), row sums from same values
        #pragma unroll
        for (int n = 0; n < 2; n++) {
            const int col = wn*16 + n*8 + 2*quad;
            const int sg0 = s0 + col, sg1 = sg0 + 1;

            float p00 = softcap_exp(c[n][0]);
            float p01 = softcap_exp(c[n][1]);
            float p10 = softcap_exp(c[n][2]);
            float p11 = softcap_exp(c[n][3]);

            p00 = (sg0 <= t_lo && sg0 + WINDOW >= t_lo) ? p00 : 0.0f;
            p01 = (sg1 <= t_lo && sg1 + WINDOW >= t_lo) ? p01 : 0.0f;
            p10 = (sg0 <= t_hi && sg0 + WINDOW >= t_hi) ? p10 : 0.0f;
            p11 = (sg1 <= t_hi && sg1 + WINDOW >= t_hi) ? p11 : 0.0f;

            p00 = __uint_as_float(f2tf32(p00));
            p01 = __uint_as_float(f2tf32(p01));
            p10 = __uint_as_float(f2tf32(p10));
            p11 = __uint_as_float(f2tf32(p11));

            *(float2*)&sm.P[r0]    [col] = make_float2(p00, p01);
            *(float2*)&sm.P[r0 + 8][col] = make_float2(p10, p11);
            lsum0 += p00 + p01;
            lsum1 += p10 + p11;
        }
        __syncthreads();   // P visible to all warps

        // ---- O += P V (warp tile 16x64, K=32 -> 4 k-chunks x 8 n-steps)
        #pragma unroll
        for (int kc = 0; kc < 4; kc++) {
            const uint32_t a0 = __float_as_uint(sm.P[r0]    [kc*8 + quad]);
            const uint32_t a1 = __float_as_uint(sm.P[r0 + 8][kc*8 + quad]);
            const uint32_t a2 = __float_as_uint(sm.P[r0]    [kc*8 + quad + 4]);
            const uint32_t a3 = __float_as_uint(sm.P[r0 + 8][kc*8 + quad + 4]);
            #pragma unroll
            for (int j = 0; j < 8; j++) {
                const int n0 = wn*64 + j*8 + grp;
                const uint32_t b0 = __float_as_uint(sm.V[kc*8 + quad]    [n0]);
                const uint32_t b1 = __float_as_uint(sm.V[kc*8 + quad + 4][n0]);
                asm volatile(
                    "mma.sync.aligned.m16n8k8.row.col.f32.tf32.tf32.f32 "
                    "{%0,%1,%2,%3}, {%4,%5,%6,%7}, {%8,%9}, {%0,%1,%2,%3};"
                    : "+f"(cpv[j][0]), "+f"(cpv[j][1]), "+f"(cpv[j][2]), "+f"(cpv[j][3])
                    : "r"(a0), "r"(a1), "r"(a2), "r"(a3), "r"(b0), "r"(b1));
            }
        }
    }

    // ---- row sums: reduce over quad (shfl), combine wn halves in smem
    lsum0 += __shfl_xor_sync(0xffffffffu, lsum0, 1);
    lsum0 += __shfl_xor_sync(0xffffffffu, lsum0, 2);
    lsum1 += __shfl_xor_sync(0xffffffffu, lsum1, 1);
    lsum1 += __shfl_xor_sync(0xffffffffu, lsum1, 2);
    __syncthreads();
    if (quad == 0) {
        sm.rowsum[wn][r0]     = lsum0;
        sm.rowsum[wn][r0 + 8] = lsum1;
    }
    __syncthreads();

    const float inv_lo = 1.0f / (sm.rowsum[0][r0]     + sm.rowsum[1][r0]);
    const float inv_hi = 1.0f / (sm.rowsum[0][r0 + 8] + sm.rowsum[1][r0 + 8]);

    float* dst_lo = E + (size_t)(rowbase + q0 + r0)     * (NH*HD) + head*HD;
    float* dst_hi = E + (size_t)(rowbase + q0 + r0 + 8) * (NH*HD) + head*HD;
    #pragma unroll
    for (int j = 0; j < 8; j++) {
        const int col = wn*64 + j*8 + 2*quad;
        *(float2*)(dst_lo + col) = make_float2(cpv[j][0] * inv_lo, cpv[j][1] * inv_lo);
        *(float2*)(dst_hi + col) = make_float2(cpv[j][2] * inv_hi, cpv[j][3] * inv_hi);
    }
}

// ---------------------------------------------------------------------------
// Launch
// ---------------------------------------------------------------------------
extern "C" void kernel_launch(void* const* d_in, const int* in_sizes, int n_in,
                              void* d_out, int out_size)
{
    const float* x  = (const float*)d_in[0];
    const float* qk = (const float*)d_in[1];
    const float* kk = (const float*)d_in[2];
    const float* vk = (const float*)d_in[3];
    const float* ok = (const float*)d_in[4];
    float* out = (float*)d_out;

    float *Q, *K, *V, *E;
    cudaGetSymbolAddress((void**)&Q, g_Q);
    cudaGetSymbolAddress((void**)&K, g_K);
    cudaGetSymbolAddress((void**)&V, g_V);
    cudaGetSymbolAddress((void**)&E, g_E);

    const int attn_smem = (int)sizeof(AttnSmem);
    cudaFuncSetAttribute(attn_kernel,
                         cudaFuncAttributeMaxDynamicSharedMemorySize, attn_smem);

    gemm_tf32<<<dim3((NH*HD)/128,  MROWS/128), 128>>>(x, qk, Q, MROWS, NH*HD,  CC);
    gemm_tf32<<<dim3((NKV*HD)/128, MROWS/128), 128>>>(x, kk, K, MROWS, NKV*HD, CC);
    gemm_tf32<<<dim3((NKV*HD)/128, MROWS/128), 128>>>(x, vk, V, MROWS, NKV*HD, CC);

    rope_kernel<<<MROWS * NH  / 4, 256>>>(Q, NH);
    rope_kernel<<<MROWS * NKV / 4, 256>>>(K, NKV);

    attn_kernel<<<dim3(TT/TQ, NH, BB), 256, attn_smem>>>(Q, K, V, E);

    gemm_tf32<<<dim3(CC/128, MROWS/128), 128>>>(E, ok, out, MROWS, CC, CC);
}

// round 17
// speedup vs baseline: 1.1204x; 1.1204x over previous
#include <cuda_runtime.h>
#include <math.h>
#include <stdint.h>

#define BB 2
#define TT 2048
#define CC 2048
#define NH 16
#define NKV 4
#define HD 128
#define GG 4
#define WINDOW 1024
#define SOFTCAP 50.0f
#define TQ 64
#define TK 32

#define MROWS (BB*TT)   // 4096

__device__ float g_Q[MROWS * (NH*HD)];
__device__ float g_K[MROWS * (NKV*HD)];
__device__ float g_V[MROWS * (NKV*HD)];
__device__ float g_E[MROWS * (NH*HD)];

__device__ __forceinline__ uint32_t f2tf32(float x) {
    uint32_t r;
    asm("cvt.rna.tf32.f32 %0, %1;" : "=r"(r) : "f"(x));
    return r;
}

// exp(50*tanh(x/50)): tanh via odd polynomial on the FMA pipe, single MUFU (ex2).
__device__ __forceinline__ float softcap_exp(float x) {
    const float z2 = x * x * (1.0f / 2500.0f);
    float p = -0.053968254f;                 // -17/315
    p = fmaf(p, z2,  0.133333333f);          //  2/15
    p = fmaf(p, z2, -0.333333333f);          // -1/3
    p = fmaf(p, z2,  1.0f);
    float y = x * p;                         // = 50*tanh(x/50)
    y = fminf(fmaxf(y, -SOFTCAP), SOFTCAP);
    float r;
    asm("ex2.approx.f32 %0, %1;" : "=f"(r) : "f"(y * 1.4426950408889634f));
    return r;
}

// ---------------------------------------------------------------------------
// Shared GEMM body (round-15 proven config): 128x128 block tile, BK=16,
// 256 threads = 8 warps (2m x 4n), warp tile 64x32, double-buffered SMEM.
// ---------------------------------------------------------------------------
__device__ __forceinline__ void gemm_body(
    const float* __restrict__ A, const float* __restrict__ B,
    float* __restrict__ C, int N, int Kd, int row0, int col0,
    float (*As)[16][132], float (*Bs)[16][132])
{
    const int tid  = threadIdx.x;
    const int lane = tid & 31;
    const int wid  = tid >> 5;
    const int wm   = wid >> 2;
    const int wn   = wid & 3;
    const int grp  = lane >> 2;
    const int tig  = lane & 3;

    const int ar = tid >> 2;
    const int kc = tid & 3;
    const int n4 = tid & 31;
    const int kr = tid >> 5;

    const float* Ap0 = A + (size_t)(row0 + ar)      * Kd + kc * 4;
    const float* Ap1 = A + (size_t)(row0 + ar + 64) * Kd + kc * 4;
    const float* Bp0 = B + (size_t)kr       * N + col0 + n4 * 4;
    const float* Bp1 = B + (size_t)(kr + 8) * N + col0 + n4 * 4;

    float acc[4][4][4];
    #pragma unroll
    for (int i = 0; i < 4; i++)
        #pragma unroll
        for (int j = 0; j < 4; j++)
            #pragma unroll
            for (int c = 0; c < 4; c++) acc[i][j][c] = 0.0f;

    float4 ga0 = *(const float4*)Ap0;
    float4 ga1 = *(const float4*)Ap1;
    float4 gb0 = *(const float4*)Bp0;
    float4 gb1 = *(const float4*)Bp1;

    {
        As[0][kc*4 + 0][ar]      = __uint_as_float(f2tf32(ga0.x));
        As[0][kc*4 + 1][ar]      = __uint_as_float(f2tf32(ga0.y));
        As[0][kc*4 + 2][ar]      = __uint_as_float(f2tf32(ga0.z));
        As[0][kc*4 + 3][ar]      = __uint_as_float(f2tf32(ga0.w));
        As[0][kc*4 + 0][ar + 64] = __uint_as_float(f2tf32(ga1.x));
        As[0][kc*4 + 1][ar + 64] = __uint_as_float(f2tf32(ga1.y));
        As[0][kc*4 + 2][ar + 64] = __uint_as_float(f2tf32(ga1.z));
        As[0][kc*4 + 3][ar + 64] = __uint_as_float(f2tf32(ga1.w));
        float4 tb;
        tb.x = __uint_as_float(f2tf32(gb0.x));
        tb.y = __uint_as_float(f2tf32(gb0.y));
        tb.z = __uint_as_float(f2tf32(gb0.z));
        tb.w = __uint_as_float(f2tf32(gb0.w));
        *(float4*)&Bs[0][kr][n4*4] = tb;
        tb.x = __uint_as_float(f2tf32(gb1.x));
        tb.y = __uint_as_float(f2tf32(gb1.y));
        tb.z = __uint_as_float(f2tf32(gb1.z));
        tb.w = __uint_as_float(f2tf32(gb1.w));
        *(float4*)&Bs[0][kr + 8][n4*4] = tb;
    }
    __syncthreads();

    const int nIter = Kd >> 4;
    for (int it = 0; it < nIter; it++) {
        const int cur = it & 1;
        const bool more = (it + 1 < nIter);

        if (more) {
            ga0 = *(const float4*)(Ap0 + (it + 1) * 16);
            ga1 = *(const float4*)(Ap1 + (it + 1) * 16);
            gb0 = *(const float4*)(Bp0 + (size_t)(it + 1) * 16 * N);
            gb1 = *(const float4*)(Bp1 + (size_t)(it + 1) * 16 * N);
        }

        #pragma unroll
        for (int kk = 0; kk < 16; kk += 8) {
            uint32_t af[4][4], bf[4][2];
            #pragma unroll
            for (int i = 0; i < 4; i++) {
                const int m0 = wm*64 + i*16 + grp;
                af[i][0] = __float_as_uint(As[cur][kk + tig]    [m0]);
                af[i][1] = __float_as_uint(As[cur][kk + tig]    [m0 + 8]);
                af[i][2] = __float_as_uint(As[cur][kk + tig + 4][m0]);
                af[i][3] = __float_as_uint(As[cur][kk + tig + 4][m0 + 8]);
            }
            #pragma unroll
            for (int j = 0; j < 4; j++) {
                const int n0 = wn*32 + j*8 + grp;
                bf[j][0] = __float_as_uint(Bs[cur][kk + tig]    [n0]);
                bf[j][1] = __float_as_uint(Bs[cur][kk + tig + 4][n0]);
            }
            #pragma unroll
            for (int i = 0; i < 4; i++)
                #pragma unroll
                for (int j = 0; j < 4; j++) {
                    asm volatile(
                        "mma.sync.aligned.m16n8k8.row.col.f32.tf32.tf32.f32 "
                        "{%0,%1,%2,%3}, {%4,%5,%6,%7}, {%8,%9}, {%0,%1,%2,%3};"
                        : "+f"(acc[i][j][0]), "+f"(acc[i][j][1]),
                          "+f"(acc[i][j][2]), "+f"(acc[i][j][3])
                        : "r"(af[i][0]), "r"(af[i][1]), "r"(af[i][2]), "r"(af[i][3]),
                          "r"(bf[j][0]), "r"(bf[j][1]));
                }
        }

        if (more) {
            const int nxt = cur ^ 1;
            As[nxt][kc*4 + 0][ar]      = __uint_as_float(f2tf32(ga0.x));
            As[nxt][kc*4 + 1][ar]      = __uint_as_float(f2tf32(ga0.y));
            As[nxt][kc*4 + 2][ar]      = __uint_as_float(f2tf32(ga0.z));
            As[nxt][kc*4 + 3][ar]      = __uint_as_float(f2tf32(ga0.w));
            As[nxt][kc*4 + 0][ar + 64] = __uint_as_float(f2tf32(ga1.x));
            As[nxt][kc*4 + 1][ar + 64] = __uint_as_float(f2tf32(ga1.y));
            As[nxt][kc*4 + 2][ar + 64] = __uint_as_float(f2tf32(ga1.z));
            As[nxt][kc*4 + 3][ar + 64] = __uint_as_float(f2tf32(ga1.w));
            float4 tb;
            tb.x = __uint_as_float(f2tf32(gb0.x));
            tb.y = __uint_as_float(f2tf32(gb0.y));
            tb.z = __uint_as_float(f2tf32(gb0.z));
            tb.w = __uint_as_float(f2tf32(gb0.w));
            *(float4*)&Bs[nxt][kr][n4*4] = tb;
            tb.x = __uint_as_float(f2tf32(gb1.x));
            tb.y = __uint_as_float(f2tf32(gb1.y));
            tb.z = __uint_as_float(f2tf32(gb1.z));
            tb.w = __uint_as_float(f2tf32(gb1.w));
            *(float4*)&Bs[nxt][kr + 8][n4*4] = tb;
        }
        __syncthreads();
    }

    #pragma unroll
    for (int i = 0; i < 4; i++) {
        const int row = row0 + wm*64 + i*16 + grp;
        #pragma unroll
        for (int j = 0; j < 4; j++) {
            const int col = col0 + wn*32 + j*8 + tig*2;
            *(float2*)(C + (size_t)row * N + col)       = make_float2(acc[i][j][0], acc[i][j][1]);
            *(float2*)(C + (size_t)(row + 8) * N + col) = make_float2(acc[i][j][2], acc[i][j][3]);
        }
    }
}

// Standalone GEMM (out projection)
__global__ __launch_bounds__(256) void gemm_tf32(
    const float* __restrict__ A, const float* __restrict__ B,
    float* __restrict__ C, int M, int N, int Kd)
{
    __shared__ float As[2][16][132];
    __shared__ float Bs[2][16][132];
    gemm_body(A, B, C, N, Kd, blockIdx.y * 128, blockIdx.x * 128, As, Bs);
}

// Fused QKV projection: grid.x = 24 (16 Q tiles + 4 K + 4 V), grid.y = 32.
__global__ __launch_bounds__(256) void qkv_gemm(
    const float* __restrict__ x,
    const float* __restrict__ qk, const float* __restrict__ kk,
    const float* __restrict__ vk,
    float* __restrict__ Q, float* __restrict__ K, float* __restrict__ V)
{
    __shared__ float As[2][16][132];
    __shared__ float Bs[2][16][132];

    const int bx = blockIdx.x;
    const float* B; float* C; int N, colt;
    if (bx < 16)      { B = qk; C = Q; N = NH*HD;  colt = bx; }
    else if (bx < 20) { B = kk; C = K; N = NKV*HD; colt = bx - 16; }
    else              { B = vk; C = V; N = NKV*HD; colt = bx - 20; }

    gemm_body(x, B, C, N, CC, blockIdx.y * 128, colt * 128, As, Bs);
}

// ---------------------------------------------------------------------------
// RoPE: 256 threads, 4 (row,head) units per block.
// ---------------------------------------------------------------------------
__global__ __launch_bounds__(256) void rope_kernel(float* data, int nheads)
{
    const int tid  = threadIdx.x;
    const int unit = blockIdx.x * 4 + (tid >> 6);
    const int i    = tid & 63;

    const int h   = unit % nheads;
    const int row = unit / nheads;
    const int t   = row % TT;

    float* p = data + (size_t)row * nheads * HD + h * HD;

    const float a = (float)t * exp2f(-(float)i * (13.287712379549449f / 64.0f));
    float c, s;
    __sincosf(a, &s, &c);

    const float x1 = p[i];
    const float x2 = p[i + 64];
    p[i]      = x1 * c - x2 * s;
    p[i + 64] = x2 * c + x1 * s;
}

// ---------------------------------------------------------------------------
// Flash-tiled attention (round-15 proven version, occ 2, half Q-hoist).
// ---------------------------------------------------------------------------
struct AttnSmem {
    float Q[TQ][132];        // tf32, pre-scaled
    float K[TK][132];        // tf32
    float V[TK][132];        // tf32
    float P[TQ][36];         // tf32 probs for current key tile
    float rowsum[2][TQ];
};

__global__ __launch_bounds__(256, 2) void attn_kernel(
    const float* __restrict__ Q, const float* __restrict__ K,
    const float* __restrict__ V, float* __restrict__ E)
{
    extern __shared__ float smem_raw[];
    AttnSmem& sm = *reinterpret_cast<AttnSmem*>(smem_raw);

    const int tid  = threadIdx.x;
    const int qt   = blockIdx.x;
    const int head = blockIdx.y;
    const int b    = blockIdx.z;
    const int kv   = head >> 2;
    const int q0   = qt * TQ;
    const int rowbase = b * TT;

    const float scale = 0.08838834764831845f;  // 128^-0.5

    // stage Q tile (scaled, tf32)
    for (int i = tid; i < 2048; i += 256) {
        const int r = i >> 5, c4 = i & 31;
        float4 v = *(const float4*)(Q + (size_t)(rowbase + q0 + r) * (NH*HD) + head*HD + c4*4);
        float4 tv;
        tv.x = __uint_as_float(f2tf32(v.x * scale));
        tv.y = __uint_as_float(f2tf32(v.y * scale));
        tv.z = __uint_as_float(f2tf32(v.z * scale));
        tv.w = __uint_as_float(f2tf32(v.w * scale));
        *(float4*)&sm.Q[r][c4*4] = tv;
    }

    const int lane = tid & 31, wid = tid >> 5;
    const int wm = wid >> 1, wn = wid & 1;
    const int grp = lane >> 2, quad = lane & 3;
    const int r0 = wm*16 + grp;
    const int t_lo = q0 + r0;
    const int t_hi = t_lo + 8;

    __syncthreads();

    // ---- hoist Q A-fragments for k-steps 0..7 into registers (once per block)
    uint32_t qa[8][4];
    #pragma unroll
    for (int ks = 0; ks < 8; ks++) {
        qa[ks][0] = __float_as_uint(sm.Q[r0]    [ks*8 + quad]);
        qa[ks][1] = __float_as_uint(sm.Q[r0 + 8][ks*8 + quad]);
        qa[ks][2] = __float_as_uint(sm.Q[r0]    [ks*8 + quad + 4]);
        qa[ks][3] = __float_as_uint(sm.Q[r0 + 8][ks*8 + quad + 4]);
    }

    int s_begin = q0 - WINDOW; if (s_begin < 0) s_begin = 0;
    const int s_end  = q0 + TQ - 1;
    const int ntiles = (s_end - s_begin) / TK + 1;

    float lsum0 = 0.0f, lsum1 = 0.0f;

    float cpv[8][4];
    #pragma unroll
    for (int j = 0; j < 8; j++)
        #pragma unroll
        for (int c = 0; c < 4; c++) cpv[j][c] = 0.0f;

    for (int tile = 0; tile < ntiles; tile++) {
        const int s0 = s_begin + tile * TK;

        __syncthreads();   // prev tile's K/V/P fully consumed

        // stage K and V tiles (both tf32): 2048 float4
        for (int i = tid; i < 2048; i += 256) {
            const int which = i >> 10;
            const int j = i & 1023;
            const int r = j >> 5, c4 = j & 31;
            int srow = s0 + r; if (srow > TT-1) srow = TT-1;
            const float* src = which ? V : K;
            float4 v = *(const float4*)(src + (size_t)(rowbase + srow) * (NKV*HD) + kv*HD + c4*4);
            float4 tv;
            tv.x = __uint_as_float(f2tf32(v.x));
            tv.y = __uint_as_float(f2tf32(v.y));
            tv.z = __uint_as_float(f2tf32(v.z));
            tv.w = __uint_as_float(f2tf32(v.w));
            if (which) *(float4*)&sm.V[r][c4*4] = tv;
            else       *(float4*)&sm.K[r][c4*4] = tv;
        }
        __syncthreads();

        // ---- S = Q K^T (warp tile 16x16)
        float c[2][4];
        #pragma unroll
        for (int n = 0; n < 2; n++)
            #pragma unroll
            for (int i = 0; i < 4; i++) c[n][i] = 0.0f;

        // k-steps 0..7: Q frags from registers
        #pragma unroll
        for (int ks = 0; ks < 8; ks++) {
            #pragma unroll
            for (int n = 0; n < 2; n++) {
                const int key = wn*16 + n*8 + grp;
                const uint32_t b0 = __float_as_uint(sm.K[key][ks*8 + quad]);
                const uint32_t b1 = __float_as_uint(sm.K[key][ks*8 + quad + 4]);
                asm volatile(
                    "mma.sync.aligned.m16n8k8.row.col.f32.tf32.tf32.f32 "
                    "{%0,%1,%2,%3}, {%4,%5,%6,%7}, {%8,%9}, {%0,%1,%2,%3};"
                    : "+f"(c[n][0]), "+f"(c[n][1]), "+f"(c[n][2]), "+f"(c[n][3])
                    : "r"(qa[ks][0]), "r"(qa[ks][1]), "r"(qa[ks][2]), "r"(qa[ks][3]),
                      "r"(b0), "r"(b1));
            }
        }
        // k-steps 8..15: Q frags from SMEM
        #pragma unroll
        for (int ks = 8; ks < 16; ks++) {
            const uint32_t a0 = __float_as_uint(sm.Q[r0]    [ks*8 + quad]);
            const uint32_t a1 = __float_as_uint(sm.Q[r0 + 8][ks*8 + quad]);
            const uint32_t a2 = __float_as_uint(sm.Q[r0]    [ks*8 + quad + 4]);
            const uint32_t a3 = __float_as_uint(sm.Q[r0 + 8][ks*8 + quad + 4]);
            #pragma unroll
            for (int n = 0; n < 2; n++) {
                const int key = wn*16 + n*8 + grp;
                const uint32_t b0 = __float_as_uint(sm.K[key][ks*8 + quad]);
                const uint32_t b1 = __float_as_uint(sm.K[key][ks*8 + quad + 4]);
                asm volatile(
                    "mma.sync.aligned.m16n8k8.row.col.f32.tf32.tf32.f32 "
                    "{%0,%1,%2,%3}, {%4,%5,%6,%7}, {%8,%9}, {%0,%1,%2,%3};"
                    : "+f"(c[n][0]), "+f"(c[n][1]), "+f"(c[n][2]), "+f"(c[n][3])
                    : "r"(a0), "r"(a1), "r"(a2), "r"(a3), "r"(b0), "r"(b1));
            }
        }

        // ---- softcap + mask + exp -> P (tf32), row sums from same values
        #pragma unroll
        for (int n = 0; n < 2; n++) {
            const int col = wn*16 + n*8 + 2*quad;
            const int sg0 = s0 + col, sg1 = sg0 + 1;

            float p00 = softcap_exp(c[n][0]);
            float p01 = softcap_exp(c[n][1]);
            float p10 = softcap_exp(c[n][2]);
            float p11 = softcap_exp(c[n][3]);

            p00 = (sg0 <= t_lo && sg0 + WINDOW >= t_lo) ? p00 : 0.0f;
            p01 = (sg1 <= t_lo && sg1 + WINDOW >= t_lo) ? p01 : 0.0f;
            p10 = (sg0 <= t_hi && sg0 + WINDOW >= t_hi) ? p10 : 0.0f;
            p11 = (sg1 <= t_hi && sg1 + WINDOW >= t_hi) ? p11 : 0.0f;

            p00 = __uint_as_float(f2tf32(p00));
            p01 = __uint_as_float(f2tf32(p01));
            p10 = __uint_as_float(f2tf32(p10));
            p11 = __uint_as_float(f2tf32(p11));

            *(float2*)&sm.P[r0]    [col] = make_float2(p00, p01);
            *(float2*)&sm.P[r0 + 8][col] = make_float2(p10, p11);
            lsum0 += p00 + p01;
            lsum1 += p10 + p11;
        }
        __syncthreads();   // P visible to all warps

        // ---- O += P V (warp tile 16x64, K=32 -> 4 k-chunks x 8 n-steps)
        #pragma unroll
        for (int kc = 0; kc < 4; kc++) {
            const uint32_t a0 = __float_as_uint(sm.P[r0]    [kc*8 + quad]);
            const uint32_t a1 = __float_as_uint(sm.P[r0 + 8][kc*8 + quad]);
            const uint32_t a2 = __float_as_uint(sm.P[r0]    [kc*8 + quad + 4]);
            const uint32_t a3 = __float_as_uint(sm.P[r0 + 8][kc*8 + quad + 4]);
            #pragma unroll
            for (int j = 0; j < 8; j++) {
                const int n0 = wn*64 + j*8 + grp;
                const uint32_t b0 = __float_as_uint(sm.V[kc*8 + quad]    [n0]);
                const uint32_t b1 = __float_as_uint(sm.V[kc*8 + quad + 4][n0]);
                asm volatile(
                    "mma.sync.aligned.m16n8k8.row.col.f32.tf32.tf32.f32 "
                    "{%0,%1,%2,%3}, {%4,%5,%6,%7}, {%8,%9}, {%0,%1,%2,%3};"
                    : "+f"(cpv[j][0]), "+f"(cpv[j][1]), "+f"(cpv[j][2]), "+f"(cpv[j][3])
                    : "r"(a0), "r"(a1), "r"(a2), "r"(a3), "r"(b0), "r"(b1));
            }
        }
    }

    // ---- row sums: reduce over quad (shfl), combine wn halves in smem
    lsum0 += __shfl_xor_sync(0xffffffffu, lsum0, 1);
    lsum0 += __shfl_xor_sync(0xffffffffu, lsum0, 2);
    lsum1 += __shfl_xor_sync(0xffffffffu, lsum1, 1);
    lsum1 += __shfl_xor_sync(0xffffffffu, lsum1, 2);
    __syncthreads();
    if (quad == 0) {
        sm.rowsum[wn][r0]     = lsum0;
        sm.rowsum[wn][r0 + 8] = lsum1;
    }
    __syncthreads();

    const float inv_lo = 1.0f / (sm.rowsum[0][r0]     + sm.rowsum[1][r0]);
    const float inv_hi = 1.0f / (sm.rowsum[0][r0 + 8] + sm.rowsum[1][r0 + 8]);

    float* dst_lo = E + (size_t)(rowbase + q0 + r0)     * (NH*HD) + head*HD;
    float* dst_hi = E + (size_t)(rowbase + q0 + r0 + 8) * (NH*HD) + head*HD;
    #pragma unroll
    for (int j = 0; j < 8; j++) {
        const int col = wn*64 + j*8 + 2*quad;
        *(float2*)(dst_lo + col) = make_float2(cpv[j][0] * inv_lo, cpv[j][1] * inv_lo);
        *(float2*)(dst_hi + col) = make_float2(cpv[j][2] * inv_hi, cpv[j][3] * inv_hi);
    }
}

// ---------------------------------------------------------------------------
// Launch
// ---------------------------------------------------------------------------
extern "C" void kernel_launch(void* const* d_in, const int* in_sizes, int n_in,
                              void* d_out, int out_size)
{
    const float* x  = (const float*)d_in[0];
    const float* qk = (const float*)d_in[1];
    const float* kk = (const float*)d_in[2];
    const float* vk = (const float*)d_in[3];
    const float* ok = (const float*)d_in[4];
    float* out = (float*)d_out;

    float *Q, *K, *V, *E;
    cudaGetSymbolAddress((void**)&Q, g_Q);
    cudaGetSymbolAddress((void**)&K, g_K);
    cudaGetSymbolAddress((void**)&V, g_V);
    cudaGetSymbolAddress((void**)&E, g_E);

    const int attn_smem = (int)sizeof(AttnSmem);
    cudaFuncSetAttribute(attn_kernel,
                         cudaFuncAttributeMaxDynamicSharedMemorySize, attn_smem);

    // Fused QKV projection: one launch, 24x32 = 768 blocks
    qkv_gemm<<<dim3(24, MROWS/128), 256>>>(x, qk, kk, vk, Q, K, V);

    rope_kernel<<<MROWS * NH  / 4, 256>>>(Q, NH);
    rope_kernel<<<MROWS * NKV / 4, 256>>>(K, NKV);

    attn_kernel<<<dim3(TT/TQ, NH, BB), 256, attn_smem>>>(Q, K, V, E);

    gemm_tf32<<<dim3(CC/128, MROWS/128), 256>>>(E, ok, out, MROWS, CC, CC);
}